// round 15
// baseline (speedup 1.0000x reference)
#include <cuda_runtime.h>
#include <cuda_bf16.h>
#include <cuda_fp16.h>
#include <math_constants.h>

#define NROW 32768
#define CDIM 256
#define NE   1024
#define MARGIN 4e-3f
#define CAP  48

// ---- static device scratch (allocation-free rule) ----
__device__ float          g_zrm[(size_t)NROW * CDIM];
__device__ __nv_bfloat16  g_ebf[(size_t)NE * CDIM];
__device__ float          g_se[NE];
__device__ int            g_cnt[NROW];
__device__ float          g_amin[NROW];
__device__ unsigned       g_list[(size_t)NROW * CAP];   // (fp16score<<16)|code
__device__ double         g_partial[512];

// ================= PTX helpers (baseline sm_80 ISA only) =================
__device__ __forceinline__ unsigned smem_u32(const void* p) {
    unsigned a;
    asm("{ .reg .u64 t; cvta.to.shared.u64 t, %1; cvt.u32.u64 %0, t; }" : "=r"(a) : "l"(p));
    return a;
}
__device__ __forceinline__ void cp16(unsigned dst, const void* src) {
    asm volatile("cp.async.cg.shared.global [%0], [%1], 16;" :: "r"(dst), "l"(src));
}
#define CP_COMMIT() asm volatile("cp.async.commit_group;" ::: "memory")
#define CP_WAIT(n)  asm volatile("cp.async.wait_group %0;" :: "n"(n) : "memory")

__device__ __forceinline__ void ldsm4(unsigned& r0, unsigned& r1, unsigned& r2, unsigned& r3,
                                      unsigned addr) {
    asm volatile("ldmatrix.sync.aligned.m8n8.x4.shared.b16 {%0,%1,%2,%3}, [%4];"
        : "=r"(r0), "=r"(r1), "=r"(r2), "=r"(r3) : "r"(addr));
}
__device__ __forceinline__ void mma16816(float* c, const unsigned* a, unsigned b0, unsigned b1) {
    asm volatile("mma.sync.aligned.m16n8k16.row.col.f32.bf16.bf16.f32 "
        "{%0,%1,%2,%3}, {%4,%5,%6,%7}, {%8,%9}, {%0,%1,%2,%3};"
        : "+f"(c[0]), "+f"(c[1]), "+f"(c[2]), "+f"(c[3])
        : "r"(a[0]), "r"(a[1]), "r"(a[2]), "r"(a[3]), "r"(b0), "r"(b1));
}
__device__ __forceinline__ unsigned fmapu(float f) {
    unsigned b = __float_as_uint(f);
    return (b & 0x80000000u) ? ~b : (b | 0x80000000u);
}
__device__ __forceinline__ float funmapu(unsigned u) {
    return (u & 0x80000000u) ? __uint_as_float(u & 0x7fffffffu) : __uint_as_float(~u);
}

// ================= fused prep: bf16 convert + per-code norms (R1-exact rounding) =================
__global__ void prep_kernel(const float* __restrict__ e) {   // grid 1024, block 64
    int j = blockIdx.x;
    float4 v = *(const float4*)&e[j * 256 + threadIdx.x * 4];
    // bf16 codebook
    __nv_bfloat16* dst = g_ebf + (size_t)j * 256 + threadIdx.x * 4;
    dst[0] = __float2bfloat16(v.x);
    dst[1] = __float2bfloat16(v.y);
    dst[2] = __float2bfloat16(v.z);
    dst[3] = __float2bfloat16(v.w);
    // se with verbatim R1 rounding
    float s = __fadd_rn(__fadd_rn(__fmul_rn(v.x,v.x), __fmul_rn(v.y,v.y)),
                        __fadd_rn(__fmul_rn(v.z,v.z), __fmul_rn(v.w,v.w)));
    for (int off = 16; off; off >>= 1) s += __shfl_down_sync(0xffffffffu, s, off);
    __shared__ float r2[2];
    if ((threadIdx.x & 31) == 0) r2[threadIdx.x >> 5] = s;
    __syncthreads();
    if (threadIdx.x == 0) g_se[j] = __fadd_rn(r2[0], r2[1]);
}

// ================= HMMA scoring + shortlist: 1024 threads, 16x32 warp tiles =================
#define SE_OFF   0
#define A_OFF    4096
#define B_OFF    (4096 + 65536)
#define MIN_OFF  (B_OFF + 131072)
#define CNT_OFF  (MIN_OFF + 512)
#define LIST_OFF (CNT_OFF + 512)
#define SMEM_T   (LIST_OFF + 128 * CAP * 4)  // 226304

__global__ void __launch_bounds__(1024) gemm_kernel(const float* __restrict__ z) {
    extern __shared__ char sm[];
    unsigned smb = smem_u32(sm);
    const int tid = threadIdx.x, l = tid & 31, w = tid >> 5;
    const int wm = w & 7, wn = w >> 3;           // 8x4 warp grid, 16x32 tiles
    const int row0 = blockIdx.x * 128;
    float* se_sm = (float*)(sm + SE_OFF);
    unsigned* sm_min = (unsigned*)(sm + MIN_OFF);
    int* sm_cnt = (int*)(sm + CNT_OFF);
    unsigned* sm_ul = (unsigned*)(sm + LIST_OFF);

    if (tid < 256) ((float4*)se_sm)[tid] = ((const float4*)g_se)[tid];

    // ---- phase 1: z slice -> zrm fp32 + bf16 A tile (32 warps, 1 tile each) ----
    // staging overlays B + min/cnt/list regions (re-initialized after)
    {
        const int b = row0 >> 10, hw0 = row0 & 1023;
        float* stg = (float*)(sm + B_OFF) + w * (36 * 32);
        int ci = w >> 2, hi = w & 3;
        #pragma unroll
        for (int i = 0; i < 8; i++) {
            int cl = i * 4 + (l >> 3);
            float4 v = *(const float4*)&z[((size_t)b << 18) + (size_t)(ci * 32 + cl) * 1024
                                          + hw0 + hi * 32 + (l & 7) * 4];
            *(float4*)&stg[cl * 36 + (l & 7) * 4] = v;
        }
        __syncwarp();
        int c = ci * 32 + l;
        #pragma unroll
        for (int rr = 0; rr < 32; rr++) {
            float v = stg[l * 36 + rr];
            int r = hi * 32 + rr;
            g_zrm[(size_t)(row0 + r) * 256 + c] = v;
            *(__nv_bfloat16*)(sm + A_OFF + r * 512 + ((c * 2) ^ ((r & 7) << 4))) =
                __float2bfloat16(v);
        }
    }
    __syncthreads();
    if (tid < 128) { sm_min[tid] = 0xFFFFFFFFu; sm_cnt[tid] = 0; }

    // ---- B chunk 0 via cp.async ----
    const char* esrc = (const char*)g_ebf;
    #pragma unroll
    for (int i = 0; i < 4; i++) {
        int f = tid + i * 1024, r = f >> 5, kb16 = f & 31;
        cp16(smb + B_OFF + r * 512 + ((kb16 * 16) ^ ((r & 7) << 4)),
             esrc + (size_t)r * 512 + kb16 * 16);
    }
    CP_COMMIT();

    const unsigned c16 = ((l >> 4) & 1) * 16;
    unsigned aBase, xA;
    {
        int r = wm * 16 + (l & 15);
        aBase = smb + A_OFF + r * 512;
        xA = c16 ^ ((r & 7) << 4);
    }
    unsigned bRow[2], xB[2];
    #pragma unroll
    for (int nfp = 0; nfp < 2; nfp++) {
        int r = wn * 32 + nfp * 16 + ((l >> 3) & 1) * 8 + (l & 7);
        bRow[nfp] = r * 512;
        xB[nfp] = c16 ^ ((r & 7) << 4);
    }

    for (int t = 0; t < 8; t++) {
        if (t < 7) {
            const char* src = esrc + (size_t)(t + 1) * 128 * 512;
            unsigned dstb = smb + B_OFF + ((t + 1) & 1) * 65536;
            #pragma unroll
            for (int i = 0; i < 4; i++) {
                int f = tid + i * 1024, r = f >> 5, kb16 = f & 31;
                cp16(dstb + r * 512 + ((kb16 * 16) ^ ((r & 7) << 4)),
                     src + (size_t)r * 512 + kb16 * 16);
            }
            CP_COMMIT();
            CP_WAIT(1);
        } else {
            CP_WAIT(0);
        }
        __syncthreads();

        float acc[4][4];
        #pragma unroll
        for (int nf = 0; nf < 4; nf++)
            #pragma unroll
            for (int q = 0; q < 4; q++) acc[nf][q] = 0.f;

        unsigned bB = smb + B_OFF + (t & 1) * 65536;

        // ---- mainloop: single-buffered frags (TLP hides latency at 8 warps/SMSP) ----
        #pragma unroll
        for (int ks = 0; ks < 16; ks++) {
            unsigned afr[4], bfr[8];
            ldsm4(afr[0], afr[1], afr[2], afr[3], aBase + ((ks << 5) ^ xA));
            #pragma unroll
            for (int nfp = 0; nfp < 2; nfp++) {
                unsigned q0, q1, q2, q3;
                ldsm4(q0, q1, q2, q3, bB + bRow[nfp] + ((ks << 5) ^ xB[nfp]));
                bfr[nfp * 4 + 0] = q0; bfr[nfp * 4 + 1] = q2;
                bfr[nfp * 4 + 2] = q1; bfr[nfp * 4 + 3] = q3;
            }
            #pragma unroll
            for (int nf = 0; nf < 4; nf++)
                mma16816(acc[nf], afr, bfr[nf * 2], bfr[nf * 2 + 1]);
        }

        // ---- epilogue: running-min push, packed u32 ----
        {
            int r0l = wm * 16 + (l >> 2);
            int r1l = r0l + 8;
            float mn0 = CUDART_INF_F, mn1 = CUDART_INF_F;
            #pragma unroll
            for (int nf = 0; nf < 4; nf++) {
                int gc = t * 128 + wn * 32 + nf * 8 + (l & 3) * 2;
                float se0 = se_sm[gc], se1 = se_sm[gc + 1];
                mn0 = fminf(mn0, fminf(fmaf(-2.f, acc[nf][0], se0),
                                       fmaf(-2.f, acc[nf][1], se1)));
                mn1 = fminf(mn1, fminf(fmaf(-2.f, acc[nf][2], se0),
                                       fmaf(-2.f, acc[nf][3], se1)));
            }
            mn0 = fminf(mn0, __shfl_xor_sync(0xffffffffu, mn0, 1));
            mn0 = fminf(mn0, __shfl_xor_sync(0xffffffffu, mn0, 2));
            mn1 = fminf(mn1, __shfl_xor_sync(0xffffffffu, mn1, 1));
            mn1 = fminf(mn1, __shfl_xor_sync(0xffffffffu, mn1, 2));
            if ((l & 3) == 0) {
                atomicMin(&sm_min[r0l], fmapu(mn0));
                atomicMin(&sm_min[r1l], fmapu(mn1));
            }
            __syncwarp();
            float thr0 = fminf(funmapu(((volatile unsigned*)sm_min)[r0l]), mn0) + MARGIN;
            float thr1 = fminf(funmapu(((volatile unsigned*)sm_min)[r1l]), mn1) + MARGIN;
            #pragma unroll
            for (int nf = 0; nf < 4; nf++) {
                int gc = t * 128 + wn * 32 + nf * 8 + (l & 3) * 2;
                float se0 = se_sm[gc], se1 = se_sm[gc + 1];
                float s00 = fmaf(-2.f, acc[nf][0], se0);
                float s01 = fmaf(-2.f, acc[nf][1], se1);
                float s10 = fmaf(-2.f, acc[nf][2], se0);
                float s11 = fmaf(-2.f, acc[nf][3], se1);
                if (s00 <= thr0) { int p = atomicAdd(&sm_cnt[r0l], 1); if (p < CAP) sm_ul[r0l * CAP + p] = ((unsigned)__half_as_ushort(__float2half_rn(s00)) << 16) | (unsigned)gc; }
                if (s01 <= thr0) { int p = atomicAdd(&sm_cnt[r0l], 1); if (p < CAP) sm_ul[r0l * CAP + p] = ((unsigned)__half_as_ushort(__float2half_rn(s01)) << 16) | (unsigned)(gc + 1); }
                if (s10 <= thr1) { int p = atomicAdd(&sm_cnt[r1l], 1); if (p < CAP) sm_ul[r1l * CAP + p] = ((unsigned)__half_as_ushort(__float2half_rn(s10)) << 16) | (unsigned)gc; }
                if (s11 <= thr1) { int p = atomicAdd(&sm_cnt[r1l], 1); if (p < CAP) sm_ul[r1l * CAP + p] = ((unsigned)__half_as_ushort(__float2half_rn(s11)) << 16) | (unsigned)(gc + 1); }
            }
        }
        __syncthreads();
    }

    // ---- lean dump: counts, final mins, used list entries ----
    #pragma unroll 1
    for (int rr = 0; rr < 4; rr++) {
        int r = w * 4 + rr, row = row0 + r;
        int cntp = sm_cnt[r];
        if (l == 0) { g_cnt[row] = cntp; g_amin[row] = funmapu(sm_min[r]); }
        int m2 = min(cntp, CAP);
        for (int i = l; i < m2; i += 32)
            g_list[(size_t)row * CAP + i] = sm_ul[r * CAP + i];
    }
}

// ================= worklist rescore: 512 CTAs, warp owns 4 rows, 8-lane dot split =================
__global__ void __launch_bounds__(512) rescore2_kernel(const float* __restrict__ emb,
                                                       float* __restrict__ out) {
    __shared__ unsigned wbuf[16][CAP];
    __shared__ double ws[16];
    const int tid = threadIdx.x, l = tid & 31, w = tid >> 5;
    const int row0 = blockIdx.x * 64;
    const int g = l >> 3, lg = l & 7;   // 4 candidate groups x 8 lanes

    double wsum = 0.0;
    #pragma unroll 1
    for (int rr = 0; rr < 4; rr++) {
        int row = row0 + w * 4 + rr;
        const float4* zp4 = (const float4*)(g_zrm + (size_t)row * CDIM);

        float4 a4 = zp4[l * 2], b4 = zp4[l * 2 + 1];
        float ss = a4.x * a4.x;
        ss = fmaf(a4.y, a4.y, ss); ss = fmaf(a4.z, a4.z, ss); ss = fmaf(a4.w, a4.w, ss);
        ss = fmaf(b4.x, b4.x, ss); ss = fmaf(b4.y, b4.y, ss);
        ss = fmaf(b4.z, b4.z, ss); ss = fmaf(b4.w, b4.w, ss);
        #pragma unroll
        for (int off = 16; off; off >>= 1) ss += __shfl_xor_sync(0xffffffffu, ss, off);
        float sz = ss;

        int cnt = g_cnt[row];
        float thr = g_amin[row] + (MARGIN + 2.5e-4f);
        bool swept = (cnt > CAP);
        int total;
        if (!swept) {
            bool k0 = false, k1 = false; unsigned e0 = 0, e1 = 0;
            if (l < cnt)      { e0 = g_list[(size_t)row * CAP + l];      k0 = __half2float(__ushort_as_half((unsigned short)(e0 >> 16))) <= thr; }
            if (32 + l < cnt) { e1 = g_list[(size_t)row * CAP + 32 + l]; k1 = __half2float(__ushort_as_half((unsigned short)(e1 >> 16))) <= thr; }
            unsigned m0 = __ballot_sync(0xffffffffu, k0);
            unsigned m1 = __ballot_sync(0xffffffffu, k1);
            if (k0) wbuf[w][__popc(m0 & ((1u << l) - 1))] = e0;
            if (k1) wbuf[w][__popc(m0) + __popc(m1 & ((1u << l) - 1))] = e1;
            total = __popc(m0) + __popc(m1);
        } else {
            total = NE;
        }
        __syncwarp();

        float bd = CUDART_INF_F; int bj = 0x7fffffff;
        for (int c0 = 0; c0 < total; c0 += 4) {
            int ci = c0 + g;
            bool valid = ci < total;
            int j = 0;
            if (valid) j = swept ? ci : (int)(wbuf[w][ci] & 0xffffu);
            float dot = 0.f, sej = 0.f;
            if (valid) {
                const float4* ep4 = (const float4*)(emb + (size_t)j * CDIM);
                sej = g_se[j];
                #pragma unroll
                for (int q = 0; q < 8; q++) {
                    float4 zv = zp4[lg + q * 8];
                    float4 ev = ep4[lg + q * 8];
                    dot = fmaf(zv.x, ev.x, dot);
                    dot = fmaf(zv.y, ev.y, dot);
                    dot = fmaf(zv.z, ev.z, dot);
                    dot = fmaf(zv.w, ev.w, dot);
                }
            }
            dot += __shfl_xor_sync(0xffffffffu, dot, 4);
            dot += __shfl_xor_sync(0xffffffffu, dot, 2);
            dot += __shfl_xor_sync(0xffffffffu, dot, 1);
            float d = valid ? fmaf(-2.f, dot, __fadd_rn(sz, sej)) : CUDART_INF_F;
            int jv = valid ? j : 0x7fffffff;
            #pragma unroll
            for (int off = 8; off <= 16; off <<= 1) {
                float od = __shfl_xor_sync(0xffffffffu, d, off);
                int   oj = __shfl_xor_sync(0xffffffffu, jv, off);
                if (od < d || (od == d && oj < jv)) { d = od; jv = oj; }
            }
            if (d < bd || (d == bd && jv < bj)) { bd = d; bj = jv; }
        }
        if (l == 0) { out[row] = (float)bj; wsum += (double)bd; }
    }
    if (l == 0) ws[w] = wsum;
    __syncthreads();
    if (tid == 0) {
        double s = 0.0;
        #pragma unroll
        for (int i = 0; i < 16; i++) s += ws[i];
        g_partial[blockIdx.x] = s;
    }
}

// ================= loss finalize =================
__global__ void loss2_kernel(float* __restrict__ out, int out_size) {
    __shared__ double s[256];
    int t = threadIdx.x;
    s[t] = g_partial[t] + g_partial[t + 256];
    __syncthreads();
    for (int off = 128; off; off >>= 1) {
        if (t < off) s[t] += s[t + off];
        __syncthreads();
    }
    if (t == 0 && out_size > NROW) {
        float m = (float)(s[0] / (double)((size_t)NROW * CDIM));
        out[NROW] = m + 0.25f * m;
    }
}

extern "C" void kernel_launch(void* const* d_in, const int* in_sizes, int n_in,
                              void* d_out, int out_size) {
    const float* z   = (const float*)d_in[0];   // (32,256,32,32) fp32
    const float* emb = (const float*)d_in[1];   // (1024,256)     fp32
    float* out = (float*)d_out;

    prep_kernel<<<1024, 64>>>(emb);

    static int smem_set = 0;
    if (!smem_set) {
        cudaFuncSetAttribute(gemm_kernel, cudaFuncAttributeMaxDynamicSharedMemorySize, SMEM_T);
        smem_set = 1;
    }
    gemm_kernel<<<256, 1024, SMEM_T>>>(z);

    rescore2_kernel<<<512, 512>>>(emb, out);
    loss2_kernel<<<1, 256>>>(out, out_size);
}

// round 16
// speedup vs baseline: 1.0436x; 1.0436x over previous
#include <cuda_runtime.h>
#include <cuda_bf16.h>
#include <cuda_fp16.h>
#include <math_constants.h>

#define NROW 32768
#define CDIM 256
#define NE   1024
#define MARGIN 4e-3f
#define CAP  48

// ---- static device scratch (allocation-free rule) ----
__device__ float          g_zrm[(size_t)NROW * CDIM];
__device__ __nv_bfloat16  g_ebf[(size_t)NE * CDIM];
__device__ float          g_se[NE];
__device__ int            g_cnt[NROW];
__device__ float          g_amin[NROW];
__device__ unsigned       g_list[(size_t)NROW * CAP];   // (fp16score<<16)|code
__device__ double         g_partial[512];
__device__ unsigned       g_done;                        // last-block ticket (self-resetting)

// ================= PTX helpers (baseline sm_80 ISA only) =================
__device__ __forceinline__ unsigned smem_u32(const void* p) {
    unsigned a;
    asm("{ .reg .u64 t; cvta.to.shared.u64 t, %1; cvt.u32.u64 %0, t; }" : "=r"(a) : "l"(p));
    return a;
}
__device__ __forceinline__ void cp16(unsigned dst, const void* src) {
    asm volatile("cp.async.cg.shared.global [%0], [%1], 16;" :: "r"(dst), "l"(src));
}
#define CP_COMMIT() asm volatile("cp.async.commit_group;" ::: "memory")
#define CP_WAIT(n)  asm volatile("cp.async.wait_group %0;" :: "n"(n) : "memory")

__device__ __forceinline__ void ldsm4(unsigned& r0, unsigned& r1, unsigned& r2, unsigned& r3,
                                      unsigned addr) {
    asm volatile("ldmatrix.sync.aligned.m8n8.x4.shared.b16 {%0,%1,%2,%3}, [%4];"
        : "=r"(r0), "=r"(r1), "=r"(r2), "=r"(r3) : "r"(addr));
}
__device__ __forceinline__ void mma16816(float* c, const unsigned* a, unsigned b0, unsigned b1) {
    asm volatile("mma.sync.aligned.m16n8k16.row.col.f32.bf16.bf16.f32 "
        "{%0,%1,%2,%3}, {%4,%5,%6,%7}, {%8,%9}, {%0,%1,%2,%3};"
        : "+f"(c[0]), "+f"(c[1]), "+f"(c[2]), "+f"(c[3])
        : "r"(a[0]), "r"(a[1]), "r"(a[2]), "r"(a[3]), "r"(b0), "r"(b1));
}
__device__ __forceinline__ unsigned fmapu(float f) {
    unsigned b = __float_as_uint(f);
    return (b & 0x80000000u) ? ~b : (b | 0x80000000u);
}
__device__ __forceinline__ float funmapu(unsigned u) {
    return (u & 0x80000000u) ? __uint_as_float(u & 0x7fffffffu) : __uint_as_float(~u);
}

// ================= fused prep: bf16 convert + per-code norms (R1-exact rounding) =================
__global__ void prep_kernel(const float* __restrict__ e) {   // grid 1024, block 64
    int j = blockIdx.x;
    float4 v = *(const float4*)&e[j * 256 + threadIdx.x * 4];
    __nv_bfloat16* dst = g_ebf + (size_t)j * 256 + threadIdx.x * 4;
    dst[0] = __float2bfloat16(v.x);
    dst[1] = __float2bfloat16(v.y);
    dst[2] = __float2bfloat16(v.z);
    dst[3] = __float2bfloat16(v.w);
    float s = __fadd_rn(__fadd_rn(__fmul_rn(v.x,v.x), __fmul_rn(v.y,v.y)),
                        __fadd_rn(__fmul_rn(v.z,v.z), __fmul_rn(v.w,v.w)));
    for (int off = 16; off; off >>= 1) s += __shfl_down_sync(0xffffffffu, s, off);
    __shared__ float r2[2];
    if ((threadIdx.x & 31) == 0) r2[threadIdx.x >> 5] = s;
    __syncthreads();
    if (threadIdx.x == 0) g_se[j] = __fadd_rn(r2[0], r2[1]);
}

// ================= HMMA scoring + shortlist (16 warps, 32x32 tiles, 1 sync/chunk) =================
#define SE_OFF   0
#define A_OFF    4096
#define B_OFF    (4096 + 65536)
#define MIN_OFF  (B_OFF + 131072)
#define CNT_OFF  (MIN_OFF + 512)
#define LIST_OFF (CNT_OFF + 512)
#define SMEM_T   (LIST_OFF + 128 * CAP * 4)  // 226304

__global__ void __launch_bounds__(512) gemm_kernel(const float* __restrict__ z) {
    extern __shared__ char sm[];
    unsigned smb = smem_u32(sm);
    const int tid = threadIdx.x, l = tid & 31, w = tid >> 5;
    const int wm = w & 3, wn = w >> 2;           // 4x4 warp grid, 32x32 tiles
    const int row0 = blockIdx.x * 128;
    float* se_sm = (float*)(sm + SE_OFF);
    unsigned* sm_min = (unsigned*)(sm + MIN_OFF);
    int* sm_cnt = (int*)(sm + CNT_OFF);
    unsigned* sm_ul = (unsigned*)(sm + LIST_OFF);

    if (tid < 256) ((float4*)se_sm)[tid] = ((const float4*)g_se)[tid];
    if (tid < 128) { sm_min[tid] = 0xFFFFFFFFu; sm_cnt[tid] = 0; }

    // ---- phase 1: z slice from ORIGINAL layout -> zrm fp32 + bf16 A tile ----
    {
        const int b = row0 >> 10, hw0 = row0 & 1023;
        float* stg = (float*)(sm + B_OFF) + w * (36 * 32);
        #pragma unroll
        for (int tt = 0; tt < 2; tt++) {
            int ti = w * 2 + tt;
            int ci = ti >> 2, hi = ti & 3;
            #pragma unroll
            for (int i = 0; i < 8; i++) {
                int cl = i * 4 + (l >> 3);
                float4 v = *(const float4*)&z[((size_t)b << 18) + (size_t)(ci * 32 + cl) * 1024
                                              + hw0 + hi * 32 + (l & 7) * 4];
                *(float4*)&stg[cl * 36 + (l & 7) * 4] = v;
            }
            __syncwarp();
            int c = ci * 32 + l;
            #pragma unroll
            for (int rr = 0; rr < 32; rr++) {
                float v = stg[l * 36 + rr];
                int r = hi * 32 + rr;
                g_zrm[(size_t)(row0 + r) * 256 + c] = v;
                *(__nv_bfloat16*)(sm + A_OFF + r * 512 + ((c * 2) ^ ((r & 7) << 4))) =
                    __float2bfloat16(v);
            }
            __syncwarp();
        }
    }
    __syncthreads();

    // ---- B chunk 0 via cp.async ----
    const char* esrc = (const char*)g_ebf;
    #pragma unroll
    for (int i = 0; i < 8; i++) {
        int f = tid + i * 512, r = f >> 5, kb16 = f & 31;
        cp16(smb + B_OFF + r * 512 + ((kb16 * 16) ^ ((r & 7) << 4)),
             esrc + (size_t)r * 512 + kb16 * 16);
    }
    CP_COMMIT();

    const unsigned c16 = ((l >> 4) & 1) * 16;
    unsigned aBase[2], xA[2];
    #pragma unroll
    for (int mf = 0; mf < 2; mf++) {
        int r = wm * 32 + mf * 16 + (l & 15);
        aBase[mf] = smb + A_OFF + r * 512;
        xA[mf] = c16 ^ ((r & 7) << 4);
    }
    unsigned bRow[2], xB[2];
    #pragma unroll
    for (int nfp = 0; nfp < 2; nfp++) {
        int r = wn * 32 + nfp * 16 + ((l >> 3) & 1) * 8 + (l & 7);
        bRow[nfp] = r * 512;
        xB[nfp] = c16 ^ ((r & 7) << 4);
    }

    for (int t = 0; t < 8; t++) {
        // wait chunk t, single barrier; issue t+1 AFTER barrier (write buf (t+1)&1
        // never conflicts with this iteration's reads of buf t&1; prior-iteration
        // readers of (t+1)&1 are fenced by this barrier)
        CP_WAIT(0);
        __syncthreads();
        if (t < 7) {
            const char* src = esrc + (size_t)(t + 1) * 128 * 512;
            unsigned dstb = smb + B_OFF + ((t + 1) & 1) * 65536;
            #pragma unroll
            for (int i = 0; i < 8; i++) {
                int f = tid + i * 512, r = f >> 5, kb16 = f & 31;
                cp16(dstb + r * 512 + ((kb16 * 16) ^ ((r & 7) << 4)),
                     src + (size_t)r * 512 + kb16 * 16);
            }
            CP_COMMIT();
        }

        float acc[2][4][4];
        #pragma unroll
        for (int mf = 0; mf < 2; mf++)
            #pragma unroll
            for (int nf = 0; nf < 4; nf++)
                #pragma unroll
                for (int q = 0; q < 4; q++) acc[mf][nf][q] = 0.f;

        unsigned bB = smb + B_OFF + (t & 1) * 65536;

        unsigned afr[2][2][4], bfr[2][8];
        #pragma unroll
        for (int mf = 0; mf < 2; mf++)
            ldsm4(afr[0][mf][0], afr[0][mf][1], afr[0][mf][2], afr[0][mf][3],
                  aBase[mf] + (0 ^ xA[mf]));
        #pragma unroll
        for (int nfp = 0; nfp < 2; nfp++) {
            unsigned q0, q1, q2, q3;
            ldsm4(q0, q1, q2, q3, bB + bRow[nfp] + (0 ^ xB[nfp]));
            bfr[0][nfp * 4 + 0] = q0; bfr[0][nfp * 4 + 1] = q2;
            bfr[0][nfp * 4 + 2] = q1; bfr[0][nfp * 4 + 3] = q3;
        }
        #pragma unroll
        for (int ks = 0; ks < 16; ks++) {
            const int cur = ks & 1, nxt = cur ^ 1;
            if (ks < 15) {
                #pragma unroll
                for (int mf = 0; mf < 2; mf++)
                    ldsm4(afr[nxt][mf][0], afr[nxt][mf][1], afr[nxt][mf][2], afr[nxt][mf][3],
                          aBase[mf] + (((ks + 1) << 5) ^ xA[mf]));
                #pragma unroll
                for (int nfp = 0; nfp < 2; nfp++) {
                    unsigned q0, q1, q2, q3;
                    ldsm4(q0, q1, q2, q3, bB + bRow[nfp] + (((ks + 1) << 5) ^ xB[nfp]));
                    bfr[nxt][nfp * 4 + 0] = q0; bfr[nxt][nfp * 4 + 1] = q2;
                    bfr[nxt][nfp * 4 + 2] = q1; bfr[nxt][nfp * 4 + 3] = q3;
                }
            }
            #pragma unroll
            for (int mf = 0; mf < 2; mf++)
                #pragma unroll
                for (int nf = 0; nf < 4; nf++)
                    mma16816(acc[mf][nf], afr[cur][mf], bfr[cur][nf * 2], bfr[cur][nf * 2 + 1]);
        }

        // ---- epilogue: running-min push, packed u32 (no trailing barrier) ----
        #pragma unroll
        for (int mf = 0; mf < 2; mf++) {
            int r0l = wm * 32 + mf * 16 + (l >> 2);
            int r1l = r0l + 8;
            float mn0 = CUDART_INF_F, mn1 = CUDART_INF_F;
            #pragma unroll
            for (int nf = 0; nf < 4; nf++) {
                int gc = t * 128 + wn * 32 + nf * 8 + (l & 3) * 2;
                float se0 = se_sm[gc], se1 = se_sm[gc + 1];
                mn0 = fminf(mn0, fminf(fmaf(-2.f, acc[mf][nf][0], se0),
                                       fmaf(-2.f, acc[mf][nf][1], se1)));
                mn1 = fminf(mn1, fminf(fmaf(-2.f, acc[mf][nf][2], se0),
                                       fmaf(-2.f, acc[mf][nf][3], se1)));
            }
            mn0 = fminf(mn0, __shfl_xor_sync(0xffffffffu, mn0, 1));
            mn0 = fminf(mn0, __shfl_xor_sync(0xffffffffu, mn0, 2));
            mn1 = fminf(mn1, __shfl_xor_sync(0xffffffffu, mn1, 1));
            mn1 = fminf(mn1, __shfl_xor_sync(0xffffffffu, mn1, 2));
            if ((l & 3) == 0) {
                atomicMin(&sm_min[r0l], fmapu(mn0));
                atomicMin(&sm_min[r1l], fmapu(mn1));
            }
            __syncwarp();
            float thr0 = fminf(funmapu(((volatile unsigned*)sm_min)[r0l]), mn0) + MARGIN;
            float thr1 = fminf(funmapu(((volatile unsigned*)sm_min)[r1l]), mn1) + MARGIN;
            #pragma unroll
            for (int nf = 0; nf < 4; nf++) {
                int gc = t * 128 + wn * 32 + nf * 8 + (l & 3) * 2;
                float se0 = se_sm[gc], se1 = se_sm[gc + 1];
                float s00 = fmaf(-2.f, acc[mf][nf][0], se0);
                float s01 = fmaf(-2.f, acc[mf][nf][1], se1);
                float s10 = fmaf(-2.f, acc[mf][nf][2], se0);
                float s11 = fmaf(-2.f, acc[mf][nf][3], se1);
                if (s00 <= thr0) { int p = atomicAdd(&sm_cnt[r0l], 1); if (p < CAP) sm_ul[r0l * CAP + p] = ((unsigned)__half_as_ushort(__float2half_rn(s00)) << 16) | (unsigned)gc; }
                if (s01 <= thr0) { int p = atomicAdd(&sm_cnt[r0l], 1); if (p < CAP) sm_ul[r0l * CAP + p] = ((unsigned)__half_as_ushort(__float2half_rn(s01)) << 16) | (unsigned)(gc + 1); }
                if (s10 <= thr1) { int p = atomicAdd(&sm_cnt[r1l], 1); if (p < CAP) sm_ul[r1l * CAP + p] = ((unsigned)__half_as_ushort(__float2half_rn(s10)) << 16) | (unsigned)gc; }
                if (s11 <= thr1) { int p = atomicAdd(&sm_cnt[r1l], 1); if (p < CAP) sm_ul[r1l * CAP + p] = ((unsigned)__half_as_ushort(__float2half_rn(s11)) << 16) | (unsigned)(gc + 1); }
            }
        }
    }
    __syncthreads();   // all epilogue pushes visible before dump

    // ---- lean dump: counts, final mins, used list entries ----
    #pragma unroll 1
    for (int rr = 0; rr < 8; rr++) {
        int r = w * 8 + rr, row = row0 + r;
        int cntp = sm_cnt[r];
        if (l == 0) { g_cnt[row] = cntp; g_amin[row] = funmapu(sm_min[r]); }
        int m2 = min(cntp, CAP);
        for (int i = l; i < m2; i += 32)
            g_list[(size_t)row * CAP + i] = sm_ul[r * CAP + i];
    }
}

// ================= worklist rescore + fused loss (last-block reduce) =================
__global__ void __launch_bounds__(512) rescore2_kernel(const float* __restrict__ emb,
                                                       float* __restrict__ out,
                                                       int out_size) {
    __shared__ unsigned wbuf[16][CAP];
    __shared__ double ws[16];
    __shared__ int s_last;
    const int tid = threadIdx.x, l = tid & 31, w = tid >> 5;
    const int row0 = blockIdx.x * 64;
    const int g = l >> 3, lg = l & 7;   // 4 candidate groups x 8 lanes

    double wsum = 0.0;
    #pragma unroll 1
    for (int rr = 0; rr < 4; rr++) {
        int row = row0 + w * 4 + rr;
        const float4* zp4 = (const float4*)(g_zrm + (size_t)row * CDIM);

        float4 a4 = zp4[l * 2], b4 = zp4[l * 2 + 1];
        float ss = a4.x * a4.x;
        ss = fmaf(a4.y, a4.y, ss); ss = fmaf(a4.z, a4.z, ss); ss = fmaf(a4.w, a4.w, ss);
        ss = fmaf(b4.x, b4.x, ss); ss = fmaf(b4.y, b4.y, ss);
        ss = fmaf(b4.z, b4.z, ss); ss = fmaf(b4.w, b4.w, ss);
        #pragma unroll
        for (int off = 16; off; off >>= 1) ss += __shfl_xor_sync(0xffffffffu, ss, off);
        float sz = ss;

        int cnt = g_cnt[row];
        float thr = g_amin[row] + (MARGIN + 2.5e-4f);
        bool swept = (cnt > CAP);
        int total;
        if (!swept) {
            bool k0 = false, k1 = false; unsigned e0 = 0, e1 = 0;
            if (l < cnt)      { e0 = g_list[(size_t)row * CAP + l];      k0 = __half2float(__ushort_as_half((unsigned short)(e0 >> 16))) <= thr; }
            if (32 + l < cnt) { e1 = g_list[(size_t)row * CAP + 32 + l]; k1 = __half2float(__ushort_as_half((unsigned short)(e1 >> 16))) <= thr; }
            unsigned m0 = __ballot_sync(0xffffffffu, k0);
            unsigned m1 = __ballot_sync(0xffffffffu, k1);
            if (k0) wbuf[w][__popc(m0 & ((1u << l) - 1))] = e0;
            if (k1) wbuf[w][__popc(m0) + __popc(m1 & ((1u << l) - 1))] = e1;
            total = __popc(m0) + __popc(m1);
        } else {
            total = NE;
        }
        __syncwarp();

        float bd = CUDART_INF_F; int bj = 0x7fffffff;
        for (int c0 = 0; c0 < total; c0 += 4) {
            int ci = c0 + g;
            bool valid = ci < total;
            int j = 0;
            if (valid) j = swept ? ci : (int)(wbuf[w][ci] & 0xffffu);
            float dot = 0.f, sej = 0.f;
            if (valid) {
                const float4* ep4 = (const float4*)(emb + (size_t)j * CDIM);
                sej = g_se[j];
                #pragma unroll
                for (int q = 0; q < 8; q++) {
                    float4 zv = zp4[lg + q * 8];
                    float4 ev = ep4[lg + q * 8];
                    dot = fmaf(zv.x, ev.x, dot);
                    dot = fmaf(zv.y, ev.y, dot);
                    dot = fmaf(zv.z, ev.z, dot);
                    dot = fmaf(zv.w, ev.w, dot);
                }
            }
            dot += __shfl_xor_sync(0xffffffffu, dot, 4);
            dot += __shfl_xor_sync(0xffffffffu, dot, 2);
            dot += __shfl_xor_sync(0xffffffffu, dot, 1);
            float d = valid ? fmaf(-2.f, dot, __fadd_rn(sz, sej)) : CUDART_INF_F;
            int jv = valid ? j : 0x7fffffff;
            #pragma unroll
            for (int off = 8; off <= 16; off <<= 1) {
                float od = __shfl_xor_sync(0xffffffffu, d, off);
                int   oj = __shfl_xor_sync(0xffffffffu, jv, off);
                if (od < d || (od == d && oj < jv)) { d = od; jv = oj; }
            }
            if (d < bd || (d == bd && jv < bj)) { bd = d; bj = jv; }
        }
        if (l == 0) { out[row] = (float)bj; wsum += (double)bd; }
    }
    if (l == 0) ws[w] = wsum;
    __syncthreads();
    if (tid == 0) {
        double s = 0.0;
        #pragma unroll
        for (int i = 0; i < 16; i++) s += ws[i];
        g_partial[blockIdx.x] = s;
        __threadfence();
        unsigned ticket = atomicAdd(&g_done, 1u);
        s_last = (ticket == 511u);
    }
    __syncthreads();

    // ---- fused loss finalize: last block reduces all 512 partials ----
    if (s_last) {
        __threadfence();
        __shared__ double red[512];
        red[tid] = g_partial[tid];
        __syncthreads();
        for (int off = 256; off; off >>= 1) {
            if (tid < off) red[tid] += red[tid + off];
            __syncthreads();
        }
        if (tid == 0) {
            if (out_size > NROW) {
                float m = (float)(red[0] / (double)((size_t)NROW * CDIM));
                out[NROW] = m + 0.25f * m;
            }
            g_done = 0;   // reset for graph replay
        }
    }
}

extern "C" void kernel_launch(void* const* d_in, const int* in_sizes, int n_in,
                              void* d_out, int out_size) {
    const float* z   = (const float*)d_in[0];   // (32,256,32,32) fp32
    const float* emb = (const float*)d_in[1];   // (1024,256)     fp32
    float* out = (float*)d_out;

    prep_kernel<<<1024, 64>>>(emb);

    static int smem_set = 0;
    if (!smem_set) {
        cudaFuncSetAttribute(gemm_kernel, cudaFuncAttributeMaxDynamicSharedMemorySize, SMEM_T);
        smem_set = 1;
    }
    gemm_kernel<<<256, 512, SMEM_T>>>(z);

    rescore2_kernel<<<512, 512>>>(emb, out, out_size);
}